// round 17
// baseline (speedup 1.0000x reference)
#include <cuda_runtime.h>
#include <cuda_bf16.h>
#include <cstdint>

#define NFIELD 39
#define VOCAB  200000
#define BATCH  16384
#define ROWSPB 128
#define THREADS 256
#define NCHUNK 10          // 10 chunks x 4 fields (kstep16) = 640 padded k

// B fragments, chunk-major: [chunk10][hl2][s4][tp4][lane32][4 u32] = 160KB
__device__ __align__(16) uint32_t BfragG[10 * 2 * 4 * 4 * 32 * 4];
// MLP weight fragments: [layer2][hl2][ks2][nt4][lane32][2 u32] = 8KB
__device__ __align__(16) uint32_t MlpFragG[2 * 2 * 2 * 4 * 32 * 2];

// Merged prep (verified R16): each thread computes its W pair once, emits hi AND lo.
__global__ void prep_all_kernel(const float* __restrict__ W1, const float* __restrict__ Wi,
                                const float* __restrict__ lin1_w, const float* __restrict__ lin2_w) {
    int j = blockIdx.x * blockDim.x + threadIdx.x;
    if (j < 20480) {
        int reg = j & 3;
        int l   = (j >> 2) & 31;
        int tp  = (j >> 7) & 3;
        int s   = (j >> 9) & 3;
        int c   = j >> 11;
        int gs = c * 4 + s;
        int t  = tp * 2 + (reg >> 1);
        int n  = t * 8 + (l >> 2);
        int k0 = gs * 16 + (l & 3) * 2 + (reg & 1) * 8;
        float v0 = 0.f, v1 = 0.f;
        if (k0 < 624)     v0 = (n < 32) ? W1[n * 624 + k0]     : Wi[(n - 32) * 624 + k0];
        if (k0 + 1 < 624) v1 = (n < 32) ? W1[n * 624 + k0 + 1] : Wi[(n - 32) * 624 + k0 + 1];
        float h0 = __bfloat162float(__float2bfloat16(v0));
        float h1 = __bfloat162float(__float2bfloat16(v1));
        uint32_t whi, wlo;
        asm("cvt.rn.bf16x2.f32 %0, %1, %2;" : "=r"(whi) : "f"(h1), "f"(h0));
        float r0 = v0 - h0, r1 = v1 - h1;
        asm("cvt.rn.bf16x2.f32 %0, %1, %2;" : "=r"(wlo) : "f"(r1), "f"(r0));
        int base = (((c * 2) * 4 + s) * 4 + tp) * 128 + l * 4 + reg;
        BfragG[base]        = whi;
        BfragG[base + 2048] = wlo;
    } else if (j < 21504) {
        int j2 = j - 20480;
        int reg = j2 & 1;
        int l   = (j2 >> 1) & 31;
        int nt  = (j2 >> 6) & 3;
        int ks  = (j2 >> 8) & 1;
        int L   = (j2 >> 9) & 1;
        int n = nt * 8 + (l >> 2);
        int k = ks * 16 + (l & 3) * 2 + reg * 8;
        const float* W = L ? lin2_w : lin1_w;
        float v0 = W[n * 32 + k];
        float v1 = W[n * 32 + k + 1];
        float h0 = __bfloat162float(__float2bfloat16(v0));
        float h1 = __bfloat162float(__float2bfloat16(v1));
        uint32_t whi, wlo;
        asm("cvt.rn.bf16x2.f32 %0, %1, %2;" : "=r"(whi) : "f"(h1), "f"(h0));
        float r0 = v0 - h0, r1 = v1 - h1;
        asm("cvt.rn.bf16x2.f32 %0, %1, %2;" : "=r"(wlo) : "f"(r1), "f"(r0));
        int base = (((L * 2) * 2 + ks) * 4 + nt) * 64 + l * 2 + reg;
        MlpFragG[base]       = whi;
        MlpFragG[base + 512] = wlo;
    }
}

__device__ __forceinline__ uint32_t packbf(float lo_elem, float hi_elem) {
    uint32_t r;
    asm("cvt.rn.bf16x2.f32 %0, %1, %2;" : "=r"(r) : "f"(hi_elem), "f"(lo_elem));
    return r;
}
__device__ __forceinline__ void mma16816(float* d, uint32_t a0, uint32_t a1, uint32_t a2, uint32_t a3,
                                         uint32_t b0, uint32_t b1) {
    asm volatile("mma.sync.aligned.m16n8k16.row.col.f32.bf16.bf16.f32 "
                 "{%0,%1,%2,%3}, {%4,%5,%6,%7}, {%8,%9}, {%0,%1,%2,%3};"
                 : "+f"(d[0]), "+f"(d[1]), "+f"(d[2]), "+f"(d[3])
                 : "r"(a0), "r"(a1), "r"(a2), "r"(a3), "r"(b0), "r"(b1));
}
__device__ __forceinline__ void ldsm4(uint32_t& r0, uint32_t& r1, uint32_t& r2, uint32_t& r3,
                                      uint32_t addr) {
    asm volatile("ldmatrix.sync.aligned.m8n8.x4.shared.b16 {%0,%1,%2,%3}, [%4];"
                 : "=r"(r0), "=r"(r1), "=r"(r2), "=r"(r3) : "r"(addr));
}

// smem: A only, warp-private: [warp8][buf2][s4][hl2][512B] = 8 x 8KB = 64KB
#define SMEM_BYTES 65536

__global__ __launch_bounds__(THREADS, 1)
void pnn_kernel(const int*   __restrict__ Xi,
                const float* __restrict__ Xv,
                const float* __restrict__ tables,
                const float* __restrict__ lin1_b,
                const float* __restrict__ lin2_b,
                const float* __restrict__ last_w,
                const float* __restrict__ last_b,
                float*       __restrict__ out) {
    extern __shared__ unsigned char smem[];
    const uint32_t sbase = (uint32_t)__cvta_generic_to_shared(smem);

    const int tid = threadIdx.x;
    const int wid = tid >> 5;        // warp owns rows [wid*16, wid*16+16), all 64 cols, full K
    const int l   = tid & 31;
    const int b0  = blockIdx.x * ROWSPB;
    const uint32_t awarp = (uint32_t)(wid * 8192);

    // warp-private quad-coop gather: g = quad, q = 16B segment of 64B row
    const int g = l >> 2;            // 0..7
    const int q = l & 3;

    // item j in 0..7: s = j>>1 (kstep/field in chunk), rl = g + (j&1)*8 (local row)
    int    nidx[3][8];
    float  nxv[3][8];
    float4 tdat[2][8];

    float acc[8][4];                 // ntile 0..7 (cols nt*8), 4 regs
    #pragma unroll
    for (int t = 0; t < 8; ++t)
        #pragma unroll
        for (int r = 0; r < 4; ++r) acc[t][r] = 0.f;

    const uint4* __restrict__ Bp = (const uint4*)BfragG;

    auto load_idx = [&](int c, int slot) {
        #pragma unroll
        for (int j = 0; j < 8; ++j) {
            int s  = j >> 1;
            int rl = g + (j & 1) * 8;
            int f  = c * 4 + s;
            int row = b0 + wid * 16 + rl;
            if (f < NFIELD) {
                nidx[slot][j] = Xi[(size_t)row * NFIELD + f];
                nxv[slot][j]  = Xv[(size_t)row * NFIELD + f];
            } else {
                nidx[slot][j] = 0;
                nxv[slot][j]  = 0.f;
            }
        }
    };
    auto table_ldg = [&](int c) {
        const int islot = c % 3, tslot = c & 1;
        #pragma unroll
        for (int j = 0; j < 8; ++j) {
            int f = c * 4 + (j >> 1);
            if (f < NFIELD)
                tdat[tslot][j] = *(((const float4*)tables) + ((long)f * VOCAB + nidx[islot][j]) * 4 + q);
            else
                tdat[tslot][j] = make_float4(0.f, 0.f, 0.f, 0.f);
        }
    };
    auto cv_store = [&](int c) {
        const int islot = c % 3, tslot = c & 1;
        const uint32_t bufo = awarp + (uint32_t)((c & 1) * 4096);
        const uint32_t inoff = (uint32_t)((q >> 1) * 256 + (q & 1) * 8);
        #pragma unroll
        for (int j = 0; j < 8; ++j) {
            int s  = j >> 1;
            int rl = g + (j & 1) * 8;
            float xv = nxv[islot][j];
            float4 t4 = tdat[tslot][j];
            float v0 = t4.x * xv, v1 = t4.y * xv, v2 = t4.z * xv, v3 = t4.w * xv;
            float r0 = v0 - __bfloat162float(__float2bfloat16(v0));
            float r1 = v1 - __bfloat162float(__float2bfloat16(v1));
            float r2 = v2 - __bfloat162float(__float2bfloat16(v2));
            float r3 = v3 - __bfloat162float(__float2bfloat16(v3));
            unsigned char* bh = smem + bufo + (s * 2 + 0) * 512 + inoff + rl * 16;
            unsigned char* bl = smem + bufo + (s * 2 + 1) * 512 + inoff + rl * 16;
            *(uint2*)bh = make_uint2(packbf(v0, v1), packbf(v2, v3));
            *(uint2*)bl = make_uint2(packbf(r0, r1), packbf(r2, r3));
        }
    };
    auto do_mma = [&](int c) {
        const uint32_t abase = sbase + awarp + (uint32_t)((c & 1) * 4096);
        const uint32_t laddr = (uint32_t)((l & 15) * 16 + (l >> 4) * 256);
        #pragma unroll
        for (int s = 0; s < 4; ++s) {
            const uint4* bb = Bp + c * 1024 + s * 128 + l;
            uint4 Bh0 = bb[0 * 512 + 0 * 32];
            uint4 Bh1 = bb[0 * 512 + 1 * 32];
            uint4 Bh2 = bb[0 * 512 + 2 * 32];
            uint4 Bh3 = bb[0 * 512 + 3 * 32];
            uint4 Bl0 = bb[1 * 512 + 0 * 32];
            uint4 Bl1 = bb[1 * 512 + 1 * 32];
            uint4 Bl2 = bb[1 * 512 + 2 * 32];
            uint4 Bl3 = bb[1 * 512 + 3 * 32];
            uint32_t ah0, ah1, ah2, ah3, al0, al1, al2, al3;
            ldsm4(ah0, ah1, ah2, ah3, abase + (s * 2 + 0) * 512 + laddr);
            ldsm4(al0, al1, al2, al3, abase + (s * 2 + 1) * 512 + laddr);
            mma16816(acc[0], ah0, ah1, ah2, ah3, Bh0.x, Bh0.y);
            mma16816(acc[1], ah0, ah1, ah2, ah3, Bh0.z, Bh0.w);
            mma16816(acc[2], ah0, ah1, ah2, ah3, Bh1.x, Bh1.y);
            mma16816(acc[3], ah0, ah1, ah2, ah3, Bh1.z, Bh1.w);
            mma16816(acc[4], ah0, ah1, ah2, ah3, Bh2.x, Bh2.y);
            mma16816(acc[5], ah0, ah1, ah2, ah3, Bh2.z, Bh2.w);
            mma16816(acc[6], ah0, ah1, ah2, ah3, Bh3.x, Bh3.y);
            mma16816(acc[7], ah0, ah1, ah2, ah3, Bh3.z, Bh3.w);
            mma16816(acc[0], ah0, ah1, ah2, ah3, Bl0.x, Bl0.y);
            mma16816(acc[1], ah0, ah1, ah2, ah3, Bl0.z, Bl0.w);
            mma16816(acc[2], ah0, ah1, ah2, ah3, Bl1.x, Bl1.y);
            mma16816(acc[3], ah0, ah1, ah2, ah3, Bl1.z, Bl1.w);
            mma16816(acc[4], ah0, ah1, ah2, ah3, Bl2.x, Bl2.y);
            mma16816(acc[5], ah0, ah1, ah2, ah3, Bl2.z, Bl2.w);
            mma16816(acc[6], ah0, ah1, ah2, ah3, Bl3.x, Bl3.y);
            mma16816(acc[7], ah0, ah1, ah2, ah3, Bl3.z, Bl3.w);
            mma16816(acc[0], al0, al1, al2, al3, Bh0.x, Bh0.y);
            mma16816(acc[1], al0, al1, al2, al3, Bh0.z, Bh0.w);
            mma16816(acc[2], al0, al1, al2, al3, Bh1.x, Bh1.y);
            mma16816(acc[3], al0, al1, al2, al3, Bh1.z, Bh1.w);
            mma16816(acc[4], al0, al1, al2, al3, Bh2.x, Bh2.y);
            mma16816(acc[5], al0, al1, al2, al3, Bh2.z, Bh2.w);
            mma16816(acc[6], al0, al1, al2, al3, Bh3.x, Bh3.y);
            mma16816(acc[7], al0, al1, al2, al3, Bh3.z, Bh3.w);
        }
    };

    // ---- prologue (warp-private) ----
    load_idx(0, 0);
    load_idx(1, 1);
    load_idx(2, 2);
    table_ldg(0);
    table_ldg(1);
    cv_store(0);
    __syncwarp();

    // ---- main loop: ZERO inter-warp sync; 8 autonomous warps ----
    #pragma unroll 1
    for (int c = 0; c < NCHUNK; ++c) {
        if (c + 3 < NCHUNK) load_idx(c + 3, (c + 3) % 3);
        if (c + 2 < NCHUNK) table_ldg(c + 2);
        do_mma(c);
        if (c + 1 < NCHUNK) cv_store(c + 1);
        __syncwarp();
    }

    // ---- register-resident epilogue: x = fo + s^2 (fo = nt 0..3, s = nt 4..7) ----
    float x[4][4];
    #pragma unroll
    for (int nt = 0; nt < 4; ++nt)
        #pragma unroll
        for (int r = 0; r < 4; ++r)
            x[nt][r] = fmaf(acc[nt + 4][r], acc[nt + 4][r], acc[nt][r]);

    // D-frag layout == MLP A-frag layout (verified R14): build hi/lo A frags
    uint32_t axh[2][4], axl[2][4];
    #pragma unroll
    for (int ks = 0; ks < 2; ++ks) {
        const float* d0 = x[ks * 2];
        const float* d1 = x[ks * 2 + 1];
        axh[ks][0] = packbf(d0[0], d0[1]);
        axh[ks][1] = packbf(d0[2], d0[3]);
        axh[ks][2] = packbf(d1[0], d1[1]);
        axh[ks][3] = packbf(d1[2], d1[3]);
        axl[ks][0] = packbf(d0[0] - __bfloat162float(__float2bfloat16(d0[0])),
                            d0[1] - __bfloat162float(__float2bfloat16(d0[1])));
        axl[ks][1] = packbf(d0[2] - __bfloat162float(__float2bfloat16(d0[2])),
                            d0[3] - __bfloat162float(__float2bfloat16(d0[3])));
        axl[ks][2] = packbf(d1[0] - __bfloat162float(__float2bfloat16(d1[0])),
                            d1[1] - __bfloat162float(__float2bfloat16(d1[1])));
        axl[ks][3] = packbf(d1[2] - __bfloat162float(__float2bfloat16(d1[2])),
                            d1[3] - __bfloat162float(__float2bfloat16(d1[3])));
    }

    const uint2* __restrict__ Mf = (const uint2*)MlpFragG;
    const int c0base = (l & 3) * 2;

    // layer 1 (bias in accumulator, consts via read-only cache)
    float a1[4][4];
    #pragma unroll
    for (int nt = 0; nt < 4; ++nt) {
        int c0 = nt * 8 + c0base;
        float blo = __ldg(lin1_b + c0), bhi = __ldg(lin1_b + c0 + 1);
        a1[nt][0] = blo; a1[nt][1] = bhi; a1[nt][2] = blo; a1[nt][3] = bhi;
    }
    #pragma unroll
    for (int ks = 0; ks < 2; ++ks)
        #pragma unroll
        for (int nt = 0; nt < 4; ++nt) {
            uint2 Bh = Mf[(((0 * 2 + 0) * 2 + ks) * 4 + nt) * 32 + l];
            uint2 Bl = Mf[(((0 * 2 + 1) * 2 + ks) * 4 + nt) * 32 + l];
            mma16816(a1[nt], axh[ks][0], axh[ks][1], axh[ks][2], axh[ks][3], Bh.x, Bh.y);
            mma16816(a1[nt], axh[ks][0], axh[ks][1], axh[ks][2], axh[ks][3], Bl.x, Bl.y);
            mma16816(a1[nt], axl[ks][0], axl[ks][1], axl[ks][2], axl[ks][3], Bh.x, Bh.y);
        }
    #pragma unroll
    for (int nt = 0; nt < 4; ++nt)
        #pragma unroll
        for (int r = 0; r < 4; ++r) a1[nt][r] = fmaxf(a1[nt][r], 0.f);

    // h1 D-frags -> layer-2 A-frags (hi + lo)
    uint32_t bh2[2][4], bl2[2][4];
    #pragma unroll
    for (int ks = 0; ks < 2; ++ks) {
        const float* d0 = a1[ks * 2];
        const float* d1 = a1[ks * 2 + 1];
        bh2[ks][0] = packbf(d0[0], d0[1]);
        bh2[ks][1] = packbf(d0[2], d0[3]);
        bh2[ks][2] = packbf(d1[0], d1[1]);
        bh2[ks][3] = packbf(d1[2], d1[3]);
        bl2[ks][0] = packbf(d0[0] - __bfloat162float(__float2bfloat16(d0[0])),
                            d0[1] - __bfloat162float(__float2bfloat16(d0[1])));
        bl2[ks][1] = packbf(d0[2] - __bfloat162float(__float2bfloat16(d0[2])),
                            d0[3] - __bfloat162float(__float2bfloat16(d0[3])));
        bl2[ks][2] = packbf(d1[0] - __bfloat162float(__float2bfloat16(d1[0])),
                            d1[1] - __bfloat162float(__float2bfloat16(d1[1])));
        bl2[ks][3] = packbf(d1[2] - __bfloat162float(__float2bfloat16(d1[2])),
                            d1[3] - __bfloat162float(__float2bfloat16(d1[3])));
    }

    // layer 2
    float a2[4][4];
    #pragma unroll
    for (int nt = 0; nt < 4; ++nt) {
        int c0 = nt * 8 + c0base;
        float blo = __ldg(lin2_b + c0), bhi = __ldg(lin2_b + c0 + 1);
        a2[nt][0] = blo; a2[nt][1] = bhi; a2[nt][2] = blo; a2[nt][3] = bhi;
    }
    #pragma unroll
    for (int ks = 0; ks < 2; ++ks)
        #pragma unroll
        for (int nt = 0; nt < 4; ++nt) {
            uint2 Bh = Mf[(((1 * 2 + 0) * 2 + ks) * 4 + nt) * 32 + l];
            uint2 Bl = Mf[(((1 * 2 + 1) * 2 + ks) * 4 + nt) * 32 + l];
            mma16816(a2[nt], bh2[ks][0], bh2[ks][1], bh2[ks][2], bh2[ks][3], Bh.x, Bh.y);
            mma16816(a2[nt], bh2[ks][0], bh2[ks][1], bh2[ks][2], bh2[ks][3], Bl.x, Bl.y);
            mma16816(a2[nt], bl2[ks][0], bl2[ks][1], bl2[ks][2], bl2[ks][3], Bh.x, Bh.y);
        }

    // final layer: relu(h2) . last_w, reduce across quad
    float s0 = 0.f, s1 = 0.f;
    #pragma unroll
    for (int nt = 0; nt < 4; ++nt) {
        int c0 = nt * 8 + c0base;
        float lw0 = __ldg(last_w + c0), lw1 = __ldg(last_w + c0 + 1);
        s0 = fmaf(fmaxf(a2[nt][0], 0.f), lw0, s0);
        s0 = fmaf(fmaxf(a2[nt][1], 0.f), lw1, s0);
        s1 = fmaf(fmaxf(a2[nt][2], 0.f), lw0, s1);
        s1 = fmaf(fmaxf(a2[nt][3], 0.f), lw1, s1);
    }
    s0 += __shfl_xor_sync(0xffffffff, s0, 1);
    s0 += __shfl_xor_sync(0xffffffff, s0, 2);
    s1 += __shfl_xor_sync(0xffffffff, s1, 1);
    s1 += __shfl_xor_sync(0xffffffff, s1, 2);
    if ((l & 3) == 0) {
        float lb = __ldg(last_b);
        out[b0 + wid * 16 + (l >> 2)]     = s0 + lb;
        out[b0 + wid * 16 + (l >> 2) + 8] = s1 + lb;
    }
}

extern "C" void kernel_launch(void* const* d_in, const int* in_sizes, int n_in,
                              void* d_out, int out_size) {
    const int*   Xi     = (const int*)  d_in[0];
    const float* Xv     = (const float*)d_in[1];
    const float* tables = (const float*)d_in[2];
    const float* W1     = (const float*)d_in[3];
    const float* Wi     = (const float*)d_in[4];
    const float* lin1_w = (const float*)d_in[5];
    const float* lin1_b = (const float*)d_in[6];
    const float* lin2_w = (const float*)d_in[7];
    const float* lin2_b = (const float*)d_in[8];
    const float* last_w = (const float*)d_in[9];
    const float* last_b = (const float*)d_in[10];
    float* out = (float*)d_out;

    static bool attr_set = false;
    if (!attr_set) {
        cudaFuncSetAttribute(pnn_kernel, cudaFuncAttributeMaxDynamicSharedMemorySize, SMEM_BYTES);
        attr_set = true;
    }

    prep_all_kernel<<<(21504 + 255) / 256, 256>>>(W1, Wi, lin1_w, lin2_w);
    pnn_kernel<<<BATCH / ROWSPB, THREADS, SMEM_BYTES>>>(
        Xi, Xv, tables, lin1_b, lin2_b, last_w, last_b, out);
}